// round 2
// baseline (speedup 1.0000x reference)
#include <cuda_runtime.h>
#include <cuda_bf16.h>
#include <math.h>

// Problem constants
#define NQ      6400
#define CDIM    128
#define SCAM    6
#define MPIX    2816     // 32*88
#define HEADS   4
#define POINTS  20
#define HSZ     32
#define WSZ     88
#define DHEAD   32
#define DANCH   4
#define OFF_W   160      // HEADS*POINTS*2
#define ATTN_W  80       // HEADS*POINTS

// Scratch (device globals -- no allocation allowed)
__device__ float g_off[NQ * OFF_W];                      // sampling offsets, already /norm
__device__ float g_aw [NQ * ATTN_W];                     // softmaxed attention weights
__device__ float g_val[SCAM * HEADS * MPIX * DHEAD];     // projected value, (s,h,pix,dh)
__device__ float g_slots[NQ * CDIM];                     // per-query accumulated slots

// ---------------------------------------------------------------------------
// Kernel A: q = query+query_pos; offsets = (q@Woff+boff)/norm ; aw = softmax(q@Wattn+battn)
// One block per query. 256 threads: 160 compute offsets, 80 compute attn logits.
// ---------------------------------------------------------------------------
__global__ void k_proj_off_attn(const float* __restrict__ query,
                                const float* __restrict__ qpos,
                                const float* __restrict__ Woff,
                                const float* __restrict__ boff,
                                const float* __restrict__ Wattn,
                                const float* __restrict__ battn) {
    const int n = blockIdx.x;
    const int t = threadIdx.x;
    __shared__ float qs[CDIM];
    __shared__ float logits[ATTN_W];

    if (t < CDIM) qs[t] = query[n * CDIM + t] + qpos[n * CDIM + t];
    __syncthreads();

    if (t < OFF_W) {
        float acc = boff[t];
        #pragma unroll 8
        for (int k = 0; k < CDIM; k++) acc = fmaf(qs[k], Woff[k * OFF_W + t], acc);
        // last dim (x,y) normalized by (W,H) = (88,32)
        const float nrm = (t & 1) ? 32.0f : 88.0f;
        g_off[n * OFF_W + t] = acc / nrm;
    } else if (t < OFF_W + ATTN_W) {
        const int o = t - OFF_W;
        float acc = battn[o];
        #pragma unroll 8
        for (int k = 0; k < CDIM; k++) acc = fmaf(qs[k], Wattn[k * ATTN_W + o], acc);
        logits[o] = acc;
    }
    __syncthreads();

    if (t < ATTN_W) {
        const int h = t / POINTS;
        float mx = -1e30f;
        #pragma unroll
        for (int p = 0; p < POINTS; p++) mx = fmaxf(mx, logits[h * POINTS + p]);
        float sum = 0.f;
        #pragma unroll
        for (int p = 0; p < POINTS; p++) sum += __expf(logits[h * POINTS + p] - mx);
        g_aw[n * ATTN_W + t] = __expf(logits[t] - mx) / sum;
    }
}

// ---------------------------------------------------------------------------
// Kernel B: value projection  val = value@Wv + bv, rearranged to (s, head, pix, dh)
// One block per (s,m) row, 128 threads = 128 output channels.
// ---------------------------------------------------------------------------
__global__ void k_proj_val(const float* __restrict__ value,
                           const float* __restrict__ Wv,
                           const float* __restrict__ bv) {
    const int row = blockIdx.x;          // 0 .. SCAM*MPIX-1
    const int s = row / MPIX;
    const int m = row % MPIX;
    const int c = threadIdx.x;
    __shared__ float vs[CDIM];

    vs[c] = value[(size_t)row * CDIM + c];   // value is (S, M, 1, C) contiguous
    __syncthreads();

    float acc = bv[c];
    #pragma unroll 8
    for (int k = 0; k < CDIM; k++) acc = fmaf(vs[k], Wv[k * CDIM + c], acc);

    const int h  = c >> 5;
    const int dh = c & 31;
    g_val[(((size_t)(s * HEADS + h)) * MPIX + m) * DHEAD + dh] = acc;
}

// ---------------------------------------------------------------------------
// Kernel C: bilinear sampling + attention-weighted accumulate over points and
// active cameras, divide by camera count. One block per query, 128 threads:
// thread t -> (head = t/32, dh = t%32).
// ---------------------------------------------------------------------------
__device__ __forceinline__ float fetch_px(const float* __restrict__ img,
                                          int x, int y, int dh) {
    if ((unsigned)x < (unsigned)WSZ && (unsigned)y < (unsigned)HSZ)
        return img[(y * WSZ + x) * DHEAD + dh];
    return 0.0f;
}

__global__ void k_sample(const float* __restrict__ refpts,   // (S,1,N,4,2)
                         const int* __restrict__ bmask) {    // (S,1,N,4) as int32 0/1
    const int n = blockIdx.x;
    const int t = threadIdx.x;
    const int h  = t >> 5;
    const int dh = t & 31;

    float acc = 0.0f;
    int cnt = 0;

    #pragma unroll
    for (int s = 0; s < SCAM; s++) {
        // any of the 4 anchor flags set? bev_mask marshaled as 4-byte ints (int32
        // 0/1 or float32 0.0/1.0 -- both are nonzero-bits iff true). One int4 load.
        const int4 mw = *reinterpret_cast<const int4*>(bmask + ((size_t)s * NQ + n) * DANCH);
        if ((mw.x | mw.y | mw.z | mw.w) == 0) continue;
        cnt++;

        const float* __restrict__ img  = g_val + ((size_t)(s * HEADS + h)) * MPIX * DHEAD;
        const float* __restrict__ refp = refpts + ((size_t)s * NQ + n) * (DANCH * 2);
        const float* __restrict__ offp = g_off + n * OFF_W + h * (POINTS * 2);
        const float* __restrict__ awp  = g_aw  + n * ATTN_W + h * POINTS;

        float cam = 0.0f;
        #pragma unroll
        for (int p = 0; p < POINTS; p++) {
            const int d = p & 3;               // anchor index
            const float ox = offp[p * 2 + 0];  // ((h*5+g)*4+d)*2 == h*40 + p*2
            const float oy = offp[p * 2 + 1];
            const float x = (refp[d * 2 + 0] + ox) * (float)WSZ - 0.5f;
            const float y = (refp[d * 2 + 1] + oy) * (float)HSZ - 0.5f;
            const float x0f = floorf(x), y0f = floorf(y);
            const float wx = x - x0f, wy = y - y0f;
            const int x0 = (int)x0f, y0 = (int)y0f;

            const float v00 = fetch_px(img, x0,     y0,     dh);
            const float v01 = fetch_px(img, x0 + 1, y0,     dh);
            const float v10 = fetch_px(img, x0,     y0 + 1, dh);
            const float v11 = fetch_px(img, x0 + 1, y0 + 1, dh);

            const float bil = v00 * (1.f - wx) * (1.f - wy)
                            + v01 * wx         * (1.f - wy)
                            + v10 * (1.f - wx) * wy
                            + v11 * wx         * wy;
            cam = fmaf(awp[p], bil, cam);
        }
        acc += cam;
    }

    acc /= fmaxf((float)cnt, 1.0f);
    g_slots[n * CDIM + t] = acc;
}

// ---------------------------------------------------------------------------
// Kernel D: out = slots@Wout + bout + residual(query)
// ---------------------------------------------------------------------------
__global__ void k_out(const float* __restrict__ query,
                      const float* __restrict__ Wout,
                      const float* __restrict__ bout,
                      float* __restrict__ out) {
    const int n = blockIdx.x;
    const int c = threadIdx.x;
    __shared__ float ss[CDIM];

    ss[c] = g_slots[n * CDIM + c];
    __syncthreads();

    float acc = bout[c];
    #pragma unroll 8
    for (int k = 0; k < CDIM; k++) acc = fmaf(ss[k], Wout[k * CDIM + c], acc);
    out[n * CDIM + c] = acc + query[n * CDIM + c];
}

// ---------------------------------------------------------------------------
// Launch. Input order per setup_inputs:
// 0 query, 1 key (unused), 2 value, 3 query_pos, 4 reference_points_cam,
// 5 bev_mask, 6 spatial_shapes, 7 level_start_index, 8 Wv, 9 bv, 10 Woff,
// 11 boff, 12 Wattn, 13 battn, 14 Wout, 15 bout
// ---------------------------------------------------------------------------
extern "C" void kernel_launch(void* const* d_in, const int* in_sizes, int n_in,
                              void* d_out, int out_size) {
    const float* query = (const float*)d_in[0];
    const float* value = (const float*)d_in[2];
    const float* qpos  = (const float*)d_in[3];
    const float* refp  = (const float*)d_in[4];
    const int*   bmask = (const int*)d_in[5];
    const float* Wv    = (const float*)d_in[8];
    const float* bv    = (const float*)d_in[9];
    const float* Woff  = (const float*)d_in[10];
    const float* boff  = (const float*)d_in[11];
    const float* Wattn = (const float*)d_in[12];
    const float* battn = (const float*)d_in[13];
    const float* Wout  = (const float*)d_in[14];
    const float* bout  = (const float*)d_in[15];
    float* out = (float*)d_out;

    k_proj_off_attn<<<NQ, 256>>>(query, qpos, Woff, boff, Wattn, battn);
    k_proj_val<<<SCAM * MPIX, CDIM>>>(value, Wv, bv);
    k_sample<<<NQ, CDIM>>>(refp, bmask);
    k_out<<<NQ, CDIM>>>(query, Wout, bout, out);
}

// round 3
// speedup vs baseline: 1.0485x; 1.0485x over previous
#include <cuda_runtime.h>
#include <cuda_bf16.h>
#include <math.h>

// Problem constants
#define NQ      6400
#define CDIM    128
#define SCAM    6
#define MPIX    2816     // 32*88
#define HEADS   4
#define POINTS  20
#define HSZ     32
#define WSZ     88
#define DHEAD   32
#define DANCH   4
#define OFF_W   160      // HEADS*POINTS*2
#define ATTN_W  80       // HEADS*POINTS
#define NCOMB   240      // OFF_W + ATTN_W

#define TM      64       // rows per GEMM block

// Scratch (device globals -- no allocation allowed)
__device__ float         g_off[NQ * OFF_W];              // sampling offsets, already /norm
__device__ float         g_aw [NQ * ATTN_W];             // softmaxed attention weights
__device__ __nv_bfloat16 g_val[SCAM * MPIX * CDIM];      // projected value, (s,pix,c) bf16
__device__ float         g_slots[NQ * CDIM];             // per-query accumulated slots

// ---------------------------------------------------------------------------
// Kernel A (tiled): q = query+query_pos; [offsets | attn logits] = q @ [Woff|Wattn]
// Block: 64 queries x 240 cols. 256 threads, micro-tile 4 rows x 15 cols.
// Epilogue: bias, /norm for offsets, per-head softmax for attn.
// smem: W (128x240) + A (64x128) = 155648 B dynamic.
// ---------------------------------------------------------------------------
__global__ void k_proj_off_attn_t(const float* __restrict__ query,
                                  const float* __restrict__ qpos,
                                  const float* __restrict__ Woff,
                                  const float* __restrict__ boff,
                                  const float* __restrict__ Wattn,
                                  const float* __restrict__ battn) {
    extern __shared__ float smem[];
    float* sW = smem;                 // [128][240]
    float* sA = smem + 128 * NCOMB;   // [64][128]

    const int n0  = blockIdx.x * TM;
    const int tid = threadIdx.x;

    for (int idx = tid; idx < 128 * NCOMB; idx += 256) {
        const int k = idx / NCOMB, n = idx - k * NCOMB;
        sW[idx] = (n < OFF_W) ? Woff[k * OFF_W + n] : Wattn[k * ATTN_W + (n - OFF_W)];
    }
    for (int idx = tid; idx < TM * 128; idx += 256) {
        const int g = n0 * CDIM + idx;
        sA[idx] = query[g] + qpos[g];
    }
    __syncthreads();

    const int ty = tid >> 4;   // 0..15 -> rows ty*4..ty*4+3
    const int tx = tid & 15;   // cols tx + 16*j, j=0..14

    float acc[4][15];
    #pragma unroll
    for (int i = 0; i < 4; i++)
        #pragma unroll
        for (int j = 0; j < 15; j++) acc[i][j] = 0.f;

    #pragma unroll 4
    for (int k = 0; k < 128; k++) {
        float a[4];
        #pragma unroll
        for (int i = 0; i < 4; i++) a[i] = sA[(ty * 4 + i) * 128 + k];
        #pragma unroll
        for (int j = 0; j < 15; j++) {
            const float w = sW[k * NCOMB + tx + 16 * j];
            #pragma unroll
            for (int i = 0; i < 4; i++) acc[i][j] = fmaf(a[i], w, acc[i][j]);
        }
    }
    __syncthreads();

    // stash results in sW as sOut[64][240]
    #pragma unroll
    for (int i = 0; i < 4; i++)
        #pragma unroll
        for (int j = 0; j < 15; j++)
            sW[(ty * 4 + i) * NCOMB + tx + 16 * j] = acc[i][j];
    __syncthreads();

    // offsets epilogue: add bias, divide by (W,H)
    for (int idx = tid; idx < TM * OFF_W; idx += 256) {
        const int r = idx / OFF_W, t = idx - r * OFF_W;
        const float v = sW[r * NCOMB + t] + boff[t];
        g_off[(n0 + r) * OFF_W + t] = v * ((t & 1) ? (1.f / 32.f) : (1.f / 88.f));
    }
    // attn softmax: 256 threads = 64 rows x 4 heads
    {
        const int r = tid >> 2, h = tid & 3;
        float lg[POINTS];
        float mx = -1e30f;
        #pragma unroll
        for (int p = 0; p < POINTS; p++) {
            lg[p] = sW[r * NCOMB + OFF_W + h * POINTS + p] + battn[h * POINTS + p];
            mx = fmaxf(mx, lg[p]);
        }
        float sum = 0.f;
        #pragma unroll
        for (int p = 0; p < POINTS; p++) { lg[p] = __expf(lg[p] - mx); sum += lg[p]; }
        const float inv = 1.f / sum;
        #pragma unroll
        for (int p = 0; p < POINTS; p++)
            g_aw[(n0 + r) * ATTN_W + h * POINTS + p] = lg[p] * inv;
    }
}

// ---------------------------------------------------------------------------
// Kernel B (tiled): val = value @ Wv + bv  -> bf16, layout (s, pix, c)
// Block: 64 rows x 128 cols, 256 threads, micro-tile 4x8.
// smem: W (128x128) + A (64x128) = 98304 B dynamic.
// ---------------------------------------------------------------------------
__global__ void k_proj_val_t(const float* __restrict__ value,
                             const float* __restrict__ Wv,
                             const float* __restrict__ bv) {
    extern __shared__ float smem[];
    float* sW = smem;                 // [128][128]
    float* sA = smem + 128 * 128;     // [64][128]

    const int n0  = blockIdx.x * TM;  // row in flattened (s*MPIX + m)
    const int tid = threadIdx.x;

    for (int idx = tid; idx < 128 * 128 / 4; idx += 256)
        reinterpret_cast<float4*>(sW)[idx] = reinterpret_cast<const float4*>(Wv)[idx];
    for (int idx = tid; idx < TM * 128 / 4; idx += 256)
        reinterpret_cast<float4*>(sA)[idx] =
            reinterpret_cast<const float4*>(value + (size_t)n0 * CDIM)[idx];
    __syncthreads();

    const int ty = tid >> 4;
    const int tx = tid & 15;

    float acc[4][8];
    #pragma unroll
    for (int i = 0; i < 4; i++)
        #pragma unroll
        for (int j = 0; j < 8; j++) acc[i][j] = 0.f;

    #pragma unroll 4
    for (int k = 0; k < 128; k++) {
        float a[4];
        #pragma unroll
        for (int i = 0; i < 4; i++) a[i] = sA[(ty * 4 + i) * 128 + k];
        #pragma unroll
        for (int j = 0; j < 8; j++) {
            const float w = sW[k * 128 + tx + 16 * j];
            #pragma unroll
            for (int i = 0; i < 4; i++) acc[i][j] = fmaf(a[i], w, acc[i][j]);
        }
    }

    #pragma unroll
    for (int i = 0; i < 4; i++) {
        const int row = n0 + ty * 4 + i;
        #pragma unroll
        for (int j = 0; j < 8; j++) {
            const int c = tx + 16 * j;
            g_val[(size_t)row * CDIM + c] = __float2bfloat16(acc[i][j] + bv[c]);
        }
    }
}

// ---------------------------------------------------------------------------
// Kernel C: bilinear sampling + attention-weighted accumulate over points and
// active cameras, divide by camera count. One block per query, 128 threads:
// thread t = channel c (head = t/32).
// ---------------------------------------------------------------------------
__device__ __forceinline__ float fetch_px(const __nv_bfloat16* __restrict__ img,
                                          int x, int y, int t) {
    if ((unsigned)x < (unsigned)WSZ && (unsigned)y < (unsigned)HSZ)
        return __bfloat162float(img[(y * WSZ + x) * CDIM + t]);
    return 0.0f;
}

__global__ void k_sample(const float* __restrict__ refpts,   // (S,1,N,4,2)
                         const int* __restrict__ bmask) {    // (S,1,N,4) 4-byte flags
    const int n = blockIdx.x;
    const int t = threadIdx.x;
    const int h = t >> 5;

    float acc = 0.0f;
    int cnt = 0;

    #pragma unroll
    for (int s = 0; s < SCAM; s++) {
        const int4 mw = *reinterpret_cast<const int4*>(bmask + ((size_t)s * NQ + n) * DANCH);
        if ((mw.x | mw.y | mw.z | mw.w) == 0) continue;
        cnt++;

        const __nv_bfloat16* __restrict__ img = g_val + (size_t)s * MPIX * CDIM;
        const float* __restrict__ refp = refpts + ((size_t)s * NQ + n) * (DANCH * 2);
        const float* __restrict__ offp = g_off + n * OFF_W + h * (POINTS * 2);
        const float* __restrict__ awp  = g_aw  + n * ATTN_W + h * POINTS;

        float cam = 0.0f;
        #pragma unroll
        for (int p = 0; p < POINTS; p++) {
            const int d = p & 3;               // anchor index
            const float ox = offp[p * 2 + 0];
            const float oy = offp[p * 2 + 1];
            const float x = (refp[d * 2 + 0] + ox) * (float)WSZ - 0.5f;
            const float y = (refp[d * 2 + 1] + oy) * (float)HSZ - 0.5f;
            const float x0f = floorf(x), y0f = floorf(y);
            const float wx = x - x0f, wy = y - y0f;
            const int x0 = (int)x0f, y0 = (int)y0f;

            const float v00 = fetch_px(img, x0,     y0,     t);
            const float v01 = fetch_px(img, x0 + 1, y0,     t);
            const float v10 = fetch_px(img, x0,     y0 + 1, t);
            const float v11 = fetch_px(img, x0 + 1, y0 + 1, t);

            const float bil = v00 * (1.f - wx) * (1.f - wy)
                            + v01 * wx         * (1.f - wy)
                            + v10 * (1.f - wx) * wy
                            + v11 * wx         * wy;
            cam = fmaf(awp[p], bil, cam);
        }
        acc += cam;
    }

    acc /= fmaxf((float)cnt, 1.0f);
    g_slots[n * CDIM + t] = acc;
}

// ---------------------------------------------------------------------------
// Kernel D (tiled): out = slots @ Wout + bout + residual(query)
// ---------------------------------------------------------------------------
__global__ void k_out_t(const float* __restrict__ query,
                        const float* __restrict__ Wout,
                        const float* __restrict__ bout,
                        float* __restrict__ out) {
    extern __shared__ float smem[];
    float* sW = smem;                 // [128][128]
    float* sA = smem + 128 * 128;     // [64][128]

    const int n0  = blockIdx.x * TM;
    const int tid = threadIdx.x;

    for (int idx = tid; idx < 128 * 128 / 4; idx += 256)
        reinterpret_cast<float4*>(sW)[idx] = reinterpret_cast<const float4*>(Wout)[idx];
    for (int idx = tid; idx < TM * 128 / 4; idx += 256)
        reinterpret_cast<float4*>(sA)[idx] =
            reinterpret_cast<const float4*>(g_slots + (size_t)n0 * CDIM)[idx];
    __syncthreads();

    const int ty = tid >> 4;
    const int tx = tid & 15;

    float acc[4][8];
    #pragma unroll
    for (int i = 0; i < 4; i++)
        #pragma unroll
        for (int j = 0; j < 8; j++) acc[i][j] = 0.f;

    #pragma unroll 4
    for (int k = 0; k < 128; k++) {
        float a[4];
        #pragma unroll
        for (int i = 0; i < 4; i++) a[i] = sA[(ty * 4 + i) * 128 + k];
        #pragma unroll
        for (int j = 0; j < 8; j++) {
            const float w = sW[k * 128 + tx + 16 * j];
            #pragma unroll
            for (int i = 0; i < 4; i++) acc[i][j] = fmaf(a[i], w, acc[i][j]);
        }
    }

    #pragma unroll
    for (int i = 0; i < 4; i++) {
        const int row = n0 + ty * 4 + i;
        #pragma unroll
        for (int j = 0; j < 8; j++) {
            const int c = tx + 16 * j;
            out[row * CDIM + c] = acc[i][j] + bout[c] + query[row * CDIM + c];
        }
    }
}

// ---------------------------------------------------------------------------
// Launch. Input order per setup_inputs:
// 0 query, 1 key (unused), 2 value, 3 query_pos, 4 reference_points_cam,
// 5 bev_mask, 6 spatial_shapes, 7 level_start_index, 8 Wv, 9 bv, 10 Woff,
// 11 boff, 12 Wattn, 13 battn, 14 Wout, 15 bout
// ---------------------------------------------------------------------------
extern "C" void kernel_launch(void* const* d_in, const int* in_sizes, int n_in,
                              void* d_out, int out_size) {
    const float* query = (const float*)d_in[0];
    const float* value = (const float*)d_in[2];
    const float* qpos  = (const float*)d_in[3];
    const float* refp  = (const float*)d_in[4];
    const int*   bmask = (const int*)d_in[5];
    const float* Wv    = (const float*)d_in[8];
    const float* bv    = (const float*)d_in[9];
    const float* Woff  = (const float*)d_in[10];
    const float* boff  = (const float*)d_in[11];
    const float* Wattn = (const float*)d_in[12];
    const float* battn = (const float*)d_in[13];
    const float* Wout  = (const float*)d_in[14];
    const float* bout  = (const float*)d_in[15];
    float* out = (float*)d_out;

    const int smemA  = (128 * NCOMB + TM * 128) * sizeof(float);   // 155648
    const int smemWv = (128 * 128 + TM * 128) * sizeof(float);     // 98304

    cudaFuncSetAttribute(k_proj_off_attn_t, cudaFuncAttributeMaxDynamicSharedMemorySize, smemA);
    cudaFuncSetAttribute(k_proj_val_t,      cudaFuncAttributeMaxDynamicSharedMemorySize, smemWv);
    cudaFuncSetAttribute(k_out_t,           cudaFuncAttributeMaxDynamicSharedMemorySize, smemWv);

    k_proj_off_attn_t<<<NQ / TM, 256, smemA>>>(query, qpos, Woff, boff, Wattn, battn);
    k_proj_val_t<<<SCAM * MPIX / TM, 256, smemWv>>>(value, Wv, bv);
    k_sample<<<NQ, CDIM>>>(refp, bmask);
    k_out_t<<<NQ / TM, 256, smemWv>>>(query, Wout, bout, out);
}

// round 5
// speedup vs baseline: 1.8624x; 1.7762x over previous
#include <cuda_runtime.h>
#include <cuda_bf16.h>
#include <math.h>

// Problem constants
#define NQ      6400
#define CDIM    128
#define SCAM    6
#define MPIX    2816     // 32*88
#define HEADS   4
#define POINTS  20
#define HSZ     32
#define WSZ     88
#define DHEAD   32
#define DANCH   4
#define OFF_W   160      // HEADS*POINTS*2
#define ATTN_W  80       // HEADS*POINTS
#define NCOMB   240      // OFF_W + ATTN_W

#define TM      64       // rows per GEMM block

// Scratch (device globals -- no allocation allowed)
__device__ float         g_off[NQ * OFF_W];              // sampling offsets, already /norm
__device__ float         g_aw [NQ * ATTN_W];             // softmaxed attention weights
__device__ __nv_bfloat16 g_val[SCAM * MPIX * CDIM];      // projected value, (s,pix,c) bf16
__device__ float         g_slots[NQ * CDIM];             // per-query accumulated slots

// ---------------------------------------------------------------------------
// Kernel A (tiled): q = query+query_pos; [offsets | attn logits] = q @ [Woff|Wattn]
// ---------------------------------------------------------------------------
__global__ void k_proj_off_attn_t(const float* __restrict__ query,
                                  const float* __restrict__ qpos,
                                  const float* __restrict__ Woff,
                                  const float* __restrict__ boff,
                                  const float* __restrict__ Wattn,
                                  const float* __restrict__ battn) {
    extern __shared__ float smem[];
    float* sW = smem;                 // [128][240]
    float* sA = smem + 128 * NCOMB;   // [64][128]

    const int n0  = blockIdx.x * TM;
    const int tid = threadIdx.x;

    for (int idx = tid; idx < 128 * NCOMB; idx += 256) {
        const int k = idx / NCOMB, n = idx - k * NCOMB;
        sW[idx] = (n < OFF_W) ? Woff[k * OFF_W + n] : Wattn[k * ATTN_W + (n - OFF_W)];
    }
    for (int idx = tid; idx < TM * 128; idx += 256) {
        const int g = n0 * CDIM + idx;
        sA[idx] = query[g] + qpos[g];
    }
    __syncthreads();

    const int ty = tid >> 4;   // rows ty*4..ty*4+3
    const int tx = tid & 15;   // cols tx + 16*j

    float acc[4][15];
    #pragma unroll
    for (int i = 0; i < 4; i++)
        #pragma unroll
        for (int j = 0; j < 15; j++) acc[i][j] = 0.f;

    #pragma unroll 4
    for (int k = 0; k < 128; k++) {
        float a[4];
        #pragma unroll
        for (int i = 0; i < 4; i++) a[i] = sA[(ty * 4 + i) * 128 + k];
        #pragma unroll
        for (int j = 0; j < 15; j++) {
            const float w = sW[k * NCOMB + tx + 16 * j];
            #pragma unroll
            for (int i = 0; i < 4; i++) acc[i][j] = fmaf(a[i], w, acc[i][j]);
        }
    }
    __syncthreads();

    #pragma unroll
    for (int i = 0; i < 4; i++)
        #pragma unroll
        for (int j = 0; j < 15; j++)
            sW[(ty * 4 + i) * NCOMB + tx + 16 * j] = acc[i][j];
    __syncthreads();

    for (int idx = tid; idx < TM * OFF_W; idx += 256) {
        const int r = idx / OFF_W, t = idx - r * OFF_W;
        const float v = sW[r * NCOMB + t] + boff[t];
        g_off[(n0 + r) * OFF_W + t] = v * ((t & 1) ? (1.f / 32.f) : (1.f / 88.f));
    }
    {
        const int r = tid >> 2, h = tid & 3;
        float lg[POINTS];
        float mx = -1e30f;
        #pragma unroll
        for (int p = 0; p < POINTS; p++) {
            lg[p] = sW[r * NCOMB + OFF_W + h * POINTS + p] + battn[h * POINTS + p];
            mx = fmaxf(mx, lg[p]);
        }
        float sum = 0.f;
        #pragma unroll
        for (int p = 0; p < POINTS; p++) { lg[p] = __expf(lg[p] - mx); sum += lg[p]; }
        const float inv = 1.f / sum;
        #pragma unroll
        for (int p = 0; p < POINTS; p++)
            g_aw[(n0 + r) * ATTN_W + h * POINTS + p] = lg[p] * inv;
    }
}

// ---------------------------------------------------------------------------
// Kernel B (tiled): val = value @ Wv + bv -> bf16 (s,pix,c). Micro-tile 4x8,
// weight cols tx*8..tx*8+7 read as 2x LDS.128, output packed uint4 stores.
// ---------------------------------------------------------------------------
__global__ void k_proj_val_t(const float* __restrict__ value,
                             const float* __restrict__ Wv,
                             const float* __restrict__ bv) {
    extern __shared__ float smem[];
    float* sW = smem;                 // [128][128]
    float* sA = smem + 128 * 128;     // [64][128]

    const int n0  = blockIdx.x * TM;
    const int tid = threadIdx.x;

    for (int idx = tid; idx < 128 * 128 / 4; idx += 256)
        reinterpret_cast<float4*>(sW)[idx] = reinterpret_cast<const float4*>(Wv)[idx];
    for (int idx = tid; idx < TM * 128 / 4; idx += 256)
        reinterpret_cast<float4*>(sA)[idx] =
            reinterpret_cast<const float4*>(value + (size_t)n0 * CDIM)[idx];
    __syncthreads();

    const int ty = tid >> 4;
    const int tx = tid & 15;

    float acc[4][8];
    #pragma unroll
    for (int i = 0; i < 4; i++)
        #pragma unroll
        for (int j = 0; j < 8; j++) acc[i][j] = 0.f;

    #pragma unroll 4
    for (int k = 0; k < 128; k++) {
        float a[4];
        #pragma unroll
        for (int i = 0; i < 4; i++) a[i] = sA[(ty * 4 + i) * 128 + k];
        const float4 w0 = *reinterpret_cast<const float4*>(&sW[k * 128 + tx * 8]);
        const float4 w1 = *reinterpret_cast<const float4*>(&sW[k * 128 + tx * 8 + 4]);
        #pragma unroll
        for (int i = 0; i < 4; i++) {
            acc[i][0] = fmaf(a[i], w0.x, acc[i][0]);
            acc[i][1] = fmaf(a[i], w0.y, acc[i][1]);
            acc[i][2] = fmaf(a[i], w0.z, acc[i][2]);
            acc[i][3] = fmaf(a[i], w0.w, acc[i][3]);
            acc[i][4] = fmaf(a[i], w1.x, acc[i][4]);
            acc[i][5] = fmaf(a[i], w1.y, acc[i][5]);
            acc[i][6] = fmaf(a[i], w1.z, acc[i][6]);
            acc[i][7] = fmaf(a[i], w1.w, acc[i][7]);
        }
    }

    const float4 b0 = *reinterpret_cast<const float4*>(&bv[tx * 8]);
    const float4 b1 = *reinterpret_cast<const float4*>(&bv[tx * 8 + 4]);
    #pragma unroll
    for (int i = 0; i < 4; i++) {
        const int row = n0 + ty * 4 + i;
        __nv_bfloat162 h0 = __floats2bfloat162_rn(acc[i][0] + b0.x, acc[i][1] + b0.y);
        __nv_bfloat162 h1 = __floats2bfloat162_rn(acc[i][2] + b0.z, acc[i][3] + b0.w);
        __nv_bfloat162 h2 = __floats2bfloat162_rn(acc[i][4] + b1.x, acc[i][5] + b1.y);
        __nv_bfloat162 h3 = __floats2bfloat162_rn(acc[i][6] + b1.z, acc[i][7] + b1.w);
        uint4 u;
        u.x = *reinterpret_cast<unsigned*>(&h0);
        u.y = *reinterpret_cast<unsigned*>(&h1);
        u.z = *reinterpret_cast<unsigned*>(&h2);
        u.w = *reinterpret_cast<unsigned*>(&h3);
        *reinterpret_cast<uint4*>(&g_val[(size_t)row * CDIM + tx * 8]) = u;
    }
}

// ---------------------------------------------------------------------------
// Kernel C: bilinear sampling. Block = query (128 threads), warp = head.
// Each warp iteration handles 2 points x 4 corners x 32 channels in one LDG.128:
//   lane = (half<<4) | (corner<<2) | chgrp ; lane loads 8 bf16 (16B) of one corner.
// Corner/point partial sums accumulate independently; single butterfly
// reduction (xor 4, 8, 16) at the end (bilinear + point/camera sums are linear).
// NOTE: all shared fills are strided loops -- OFF_W (160) > blockDim (128).
// ---------------------------------------------------------------------------
__global__ void k_sample(const float* __restrict__ refpts,   // (S,1,N,4,2)
                         const int* __restrict__ bmask) {    // (S,1,N,4) 4-byte flags
    const int n    = blockIdx.x;
    const int t    = threadIdx.x;
    const int h    = t >> 5;
    const int lane = t & 31;
    const int half = lane >> 4;        // which point of the pair
    const int c2   = (lane >> 2) & 3;  // bilinear corner
    const int dx   = c2 & 1, dy = c2 >> 1;
    const int g2   = lane & 3;         // channel group of 8

    __shared__ float sOff[OFF_W];
    __shared__ float sAw[ATTN_W];
    __shared__ float sRef[SCAM * 8];
    __shared__ int   sAct[SCAM];
    __shared__ int   sCnt;

    for (int i = t; i < OFF_W; i += 128)  sOff[i] = g_off[n * OFF_W + i];
    for (int i = t; i < ATTN_W; i += 128) sAw[i]  = g_aw[n * ATTN_W + i];
    for (int i = t; i < SCAM * 8; i += 128) {
        const int s = i >> 3, e = i & 7;
        sRef[i] = refpts[((size_t)s * NQ + n) * 8 + e];
    }
    if (t == 0) {
        int cnt = 0;
        #pragma unroll
        for (int s = 0; s < SCAM; s++) {
            const int4 mw = *reinterpret_cast<const int4*>(bmask + ((size_t)s * NQ + n) * DANCH);
            if (mw.x | mw.y | mw.z | mw.w) sAct[cnt++] = s;
        }
        sCnt = cnt;
    }
    __syncthreads();

    float acc[8];
    #pragma unroll
    for (int i = 0; i < 8; i++) acc[i] = 0.f;

    const int cnt = sCnt;
    for (int j = 0; j < cnt; j++) {
        const int s = sAct[j];
        const __nv_bfloat16* __restrict__ imgb =
            g_val + (size_t)s * MPIX * CDIM + h * DHEAD + g2 * 8;
        const float* __restrict__ rf = &sRef[s * 8];

        #pragma unroll
        for (int pp = 0; pp < POINTS; pp += 2) {
            const int p = pp + half;
            const int d = p & 3;
            const float x = (rf[d * 2 + 0] + sOff[h * 40 + p * 2 + 0]) * 88.f - 0.5f;
            const float y = (rf[d * 2 + 1] + sOff[h * 40 + p * 2 + 1]) * 32.f - 0.5f;
            const float x0f = floorf(x), y0f = floorf(y);
            const float wx = x - x0f, wy = y - y0f;
            const int xx = (int)x0f + dx;
            const int yy = (int)y0f + dy;
            const float wc = (dx ? wx : 1.f - wx) * (dy ? wy : 1.f - wy) * sAw[h * POINTS + p];

            if ((unsigned)xx < (unsigned)WSZ && (unsigned)yy < (unsigned)HSZ) {
                const uint4 raw = *reinterpret_cast<const uint4*>(imgb + (yy * WSZ + xx) * CDIM);
                const float2 f0 = __bfloat1622float2(*reinterpret_cast<const __nv_bfloat162*>(&raw.x));
                const float2 f1 = __bfloat1622float2(*reinterpret_cast<const __nv_bfloat162*>(&raw.y));
                const float2 f2 = __bfloat1622float2(*reinterpret_cast<const __nv_bfloat162*>(&raw.z));
                const float2 f3 = __bfloat1622float2(*reinterpret_cast<const __nv_bfloat162*>(&raw.w));
                acc[0] = fmaf(wc, f0.x, acc[0]);
                acc[1] = fmaf(wc, f0.y, acc[1]);
                acc[2] = fmaf(wc, f1.x, acc[2]);
                acc[3] = fmaf(wc, f1.y, acc[3]);
                acc[4] = fmaf(wc, f2.x, acc[4]);
                acc[5] = fmaf(wc, f2.y, acc[5]);
                acc[6] = fmaf(wc, f3.x, acc[6]);
                acc[7] = fmaf(wc, f3.y, acc[7]);
            }
        }
    }

    // reduce over corners (xor 4, 8) and point-halves (xor 16)
    #pragma unroll
    for (int m = 4; m <= 16; m <<= 1)
        #pragma unroll
        for (int i = 0; i < 8; i++)
            acc[i] += __shfl_xor_sync(0xffffffffu, acc[i], m);

    if (lane < 4) {
        const float inv = 1.f / fmaxf((float)cnt, 1.0f);
        float4 o0 = make_float4(acc[0] * inv, acc[1] * inv, acc[2] * inv, acc[3] * inv);
        float4 o1 = make_float4(acc[4] * inv, acc[5] * inv, acc[6] * inv, acc[7] * inv);
        float* dst = g_slots + (size_t)n * CDIM + h * DHEAD + g2 * 8;
        *reinterpret_cast<float4*>(dst)     = o0;
        *reinterpret_cast<float4*>(dst + 4) = o1;
    }
}

// ---------------------------------------------------------------------------
// Kernel D (tiled): out = slots @ Wout + bout + residual(query). Same micro
// structure as kernel B, fp32 output.
// ---------------------------------------------------------------------------
__global__ void k_out_t(const float* __restrict__ query,
                        const float* __restrict__ Wout,
                        const float* __restrict__ bout,
                        float* __restrict__ out) {
    extern __shared__ float smem[];
    float* sW = smem;                 // [128][128]
    float* sA = smem + 128 * 128;     // [64][128]

    const int n0  = blockIdx.x * TM;
    const int tid = threadIdx.x;

    for (int idx = tid; idx < 128 * 128 / 4; idx += 256)
        reinterpret_cast<float4*>(sW)[idx] = reinterpret_cast<const float4*>(Wout)[idx];
    for (int idx = tid; idx < TM * 128 / 4; idx += 256)
        reinterpret_cast<float4*>(sA)[idx] =
            reinterpret_cast<const float4*>(g_slots + (size_t)n0 * CDIM)[idx];
    __syncthreads();

    const int ty = tid >> 4;
    const int tx = tid & 15;

    float acc[4][8];
    #pragma unroll
    for (int i = 0; i < 4; i++)
        #pragma unroll
        for (int j = 0; j < 8; j++) acc[i][j] = 0.f;

    #pragma unroll 4
    for (int k = 0; k < 128; k++) {
        float a[4];
        #pragma unroll
        for (int i = 0; i < 4; i++) a[i] = sA[(ty * 4 + i) * 128 + k];
        const float4 w0 = *reinterpret_cast<const float4*>(&sW[k * 128 + tx * 8]);
        const float4 w1 = *reinterpret_cast<const float4*>(&sW[k * 128 + tx * 8 + 4]);
        #pragma unroll
        for (int i = 0; i < 4; i++) {
            acc[i][0] = fmaf(a[i], w0.x, acc[i][0]);
            acc[i][1] = fmaf(a[i], w0.y, acc[i][1]);
            acc[i][2] = fmaf(a[i], w0.z, acc[i][2]);
            acc[i][3] = fmaf(a[i], w0.w, acc[i][3]);
            acc[i][4] = fmaf(a[i], w1.x, acc[i][4]);
            acc[i][5] = fmaf(a[i], w1.y, acc[i][5]);
            acc[i][6] = fmaf(a[i], w1.z, acc[i][6]);
            acc[i][7] = fmaf(a[i], w1.w, acc[i][7]);
        }
    }

    const float4 b0 = *reinterpret_cast<const float4*>(&bout[tx * 8]);
    const float4 b1 = *reinterpret_cast<const float4*>(&bout[tx * 8 + 4]);
    #pragma unroll
    for (int i = 0; i < 4; i++) {
        const int row = n0 + ty * 4 + i;
        const float4 q0 = *reinterpret_cast<const float4*>(&query[row * CDIM + tx * 8]);
        const float4 q1 = *reinterpret_cast<const float4*>(&query[row * CDIM + tx * 8 + 4]);
        float4 o0 = make_float4(acc[i][0] + b0.x + q0.x, acc[i][1] + b0.y + q0.y,
                                acc[i][2] + b0.z + q0.z, acc[i][3] + b0.w + q0.w);
        float4 o1 = make_float4(acc[i][4] + b1.x + q1.x, acc[i][5] + b1.y + q1.y,
                                acc[i][6] + b1.z + q1.z, acc[i][7] + b1.w + q1.w);
        *reinterpret_cast<float4*>(&out[row * CDIM + tx * 8])     = o0;
        *reinterpret_cast<float4*>(&out[row * CDIM + tx * 8 + 4]) = o1;
    }
}

// ---------------------------------------------------------------------------
// Launch. Input order per setup_inputs:
// 0 query, 1 key (unused), 2 value, 3 query_pos, 4 reference_points_cam,
// 5 bev_mask, 6 spatial_shapes, 7 level_start_index, 8 Wv, 9 bv, 10 Woff,
// 11 boff, 12 Wattn, 13 battn, 14 Wout, 15 bout
// ---------------------------------------------------------------------------
extern "C" void kernel_launch(void* const* d_in, const int* in_sizes, int n_in,
                              void* d_out, int out_size) {
    const float* query = (const float*)d_in[0];
    const float* value = (const float*)d_in[2];
    const float* qpos  = (const float*)d_in[3];
    const float* refp  = (const float*)d_in[4];
    const int*   bmask = (const int*)d_in[5];
    const float* Wv    = (const float*)d_in[8];
    const float* bv    = (const float*)d_in[9];
    const float* Woff  = (const float*)d_in[10];
    const float* boff  = (const float*)d_in[11];
    const float* Wattn = (const float*)d_in[12];
    const float* battn = (const float*)d_in[13];
    const float* Wout  = (const float*)d_in[14];
    const float* bout  = (const float*)d_in[15];
    float* out = (float*)d_out;

    const int smemA  = (128 * NCOMB + TM * 128) * sizeof(float);   // 155648
    const int smemWv = (128 * 128 + TM * 128) * sizeof(float);     // 98304

    cudaFuncSetAttribute(k_proj_off_attn_t, cudaFuncAttributeMaxDynamicSharedMemorySize, smemA);
    cudaFuncSetAttribute(k_proj_val_t,      cudaFuncAttributeMaxDynamicSharedMemorySize, smemWv);
    cudaFuncSetAttribute(k_out_t,           cudaFuncAttributeMaxDynamicSharedMemorySize, smemWv);

    k_proj_off_attn_t<<<NQ / TM, 256, smemA>>>(query, qpos, Woff, boff, Wattn, battn);
    k_proj_val_t<<<SCAM * MPIX / TM, 256, smemWv>>>(value, Wv, bv);
    k_sample<<<NQ, CDIM>>>(refp, bmask);
    k_out_t<<<NQ / TM, 256, smemWv>>>(query, Wout, bout, out);
}